// round 1
// baseline (speedup 1.0000x reference)
#include <cuda_runtime.h>
#include <math.h>

#define T_  2048
#define D_  2048
#define H_  16
#define HD_ 128

// Scratch (allocation-free rule: __device__ globals)
__device__ float g_Q[T_ * D_];
__device__ float g_K[T_ * D_];
__device__ float g_V[T_ * D_];
__device__ float g_A[T_ * D_];

// ---------------------------------------------------------------------------
// SGEMM: C[2048x2048] = A[2048x2048] @ B[2048x2048], all row-major fp32.
// 128x128 block tile, BK=8, 256 threads, 8x8 per-thread micro-tile.
// ---------------------------------------------------------------------------
__global__ __launch_bounds__(256) void sgemm2048(const float* __restrict__ A,
                                                 const float* __restrict__ B,
                                                 float* __restrict__ C)
{
    const int K = D_;
    const int N = D_;
    __shared__ float As[8][128];
    __shared__ float Bs[8][128];

    const int tid = threadIdx.x;
    const int br = blockIdx.y * 128;
    const int bc = blockIdx.x * 128;

    const int arow = tid >> 1;          // 0..127
    const int acol = (tid & 1) << 2;    // 0 or 4
    const int brow = tid >> 5;          // 0..7
    const int bcol = (tid & 31) << 2;   // 0..124

    const int tr = (tid >> 4) << 3;     // 0..120 step 8
    const int tc = (tid & 15) << 3;     // 0..120 step 8

    float acc[8][8];
#pragma unroll
    for (int i = 0; i < 8; i++)
#pragma unroll
        for (int j = 0; j < 8; j++) acc[i][j] = 0.0f;

    float ra[8], rb[8];

    for (int k0 = 0; k0 < K; k0 += 8) {
        float4 av = *(const float4*)&A[(br + arow) * K + k0 + acol];
        float4 bv = *(const float4*)&B[(k0 + brow) * N + bc + bcol];
        As[acol + 0][arow] = av.x;
        As[acol + 1][arow] = av.y;
        As[acol + 2][arow] = av.z;
        As[acol + 3][arow] = av.w;
        *(float4*)&Bs[brow][bcol] = bv;
        __syncthreads();

#pragma unroll
        for (int k = 0; k < 8; ++k) {
            *(float4*)&ra[0] = *(float4*)&As[k][tr];
            *(float4*)&ra[4] = *(float4*)&As[k][tr + 4];
            *(float4*)&rb[0] = *(float4*)&Bs[k][tc];
            *(float4*)&rb[4] = *(float4*)&Bs[k][tc + 4];
#pragma unroll
            for (int i = 0; i < 8; i++)
#pragma unroll
                for (int j = 0; j < 8; j++)
                    acc[i][j] = fmaf(ra[i], rb[j], acc[i][j]);
        }
        __syncthreads();
    }

#pragma unroll
    for (int i = 0; i < 8; i++) {
        float4 o0 = make_float4(acc[i][0], acc[i][1], acc[i][2], acc[i][3]);
        float4 o1 = make_float4(acc[i][4], acc[i][5], acc[i][6], acc[i][7]);
        *(float4*)&C[(br + tr + i) * N + bc + tc] = o0;
        *(float4*)&C[(br + tr + i) * N + bc + tc + 4] = o1;
    }
}

// ---------------------------------------------------------------------------
// RoPE (in-place) on Q and K. One thread handles the (d, d+64) pair for both.
// ---------------------------------------------------------------------------
__global__ __launch_bounds__(256) void rope_kernel(float* __restrict__ Q,
                                                   float* __restrict__ K,
                                                   const float* __restrict__ sin_t,
                                                   const float* __restrict__ cos_t)
{
    int idx = blockIdx.x * blockDim.x + threadIdx.x;
    if (idx >= T_ * H_ * 64) return;
    int d = idx & 63;
    int h = (idx >> 6) & (H_ - 1);
    int t = idx >> 10;
    int base = t * D_ + h * HD_;

    float s1 = sin_t[t * HD_ + d];
    float c1 = cos_t[t * HD_ + d];
    float s2 = sin_t[t * HD_ + d + 64];
    float c2 = cos_t[t * HD_ + d + 64];

    float q1 = Q[base + d];
    float q2 = Q[base + d + 64];
    Q[base + d]      = q1 * c1 - q2 * s1;
    Q[base + d + 64] = q2 * c2 + q1 * s2;

    float k1 = K[base + d];
    float k2 = K[base + d + 64];
    K[base + d]      = k1 * c1 - k2 * s1;
    K[base + d + 64] = k2 * c2 + k1 * s2;
}

// ---------------------------------------------------------------------------
// Flash-style attention with causal + same-doc mask.
// Block = (query tile of 64, head). 256 threads.
// Key tiles of 64, online softmax, O accumulated in registers (4x8/thread).
// Doc-aware tile skip: doc_ids sorted, so if doc[k_last] < doc[q_first] the
// whole tile is masked.
// ---------------------------------------------------------------------------
#define BM 64
#define BN 64
#define LDK 132   // padded row stride for K tile (bank conflicts)
#define LDP 65    // padded row stride for P tile

__global__ __launch_bounds__(256) void attn_kernel(const float* __restrict__ Q,
                                                   const float* __restrict__ K,
                                                   const float* __restrict__ V,
                                                   const int* __restrict__ doc,
                                                   float* __restrict__ O)
{
    extern __shared__ float sm[];
    float* Qs = sm;                      // 64 * 128
    float* Ks = Qs + BM * HD_;           // 64 * 132
    float* Vs = Ks + BN * LDK;           // 64 * 128
    float* Ps = Vs + BN * HD_;           // 64 * 65
    float* rescale = Ps + BM * LDP;      // 64
    float* lrow = rescale + BM;          // 64
    __shared__ int qdoc[BM];
    __shared__ int kdoc[BN];

    const int h = blockIdx.y;
    const int qt = blockIdx.x;
    const int qbase = qt * BM;
    const int tid = threadIdx.x;

    const float scale = 0.08838834764831845f;  // 1/sqrt(128)

    // Load Q tile (pre-scaled)
    for (int i = tid; i < BM * HD_ / 4; i += 256) {
        int r = i >> 5;
        int c4 = (i & 31) << 2;
        float4 v = *(const float4*)&Q[(qbase + r) * D_ + h * HD_ + c4];
        v.x *= scale; v.y *= scale; v.z *= scale; v.w *= scale;
        *(float4*)&Qs[r * HD_ + c4] = v;
    }
    if (tid < BM) qdoc[tid] = doc[qbase + tid];

    // S-phase mapping: rows sr + {0,16,32,48}, cols sc + {0,16,32,48}
    const int sr = tid >> 4;   // 0..15
    const int sc = tid & 15;   // 0..15
    // PV-phase mapping: rows rg + {0,16,32,48}, cols c0..c0+7
    const int rg = tid >> 4;
    const int c0 = (tid & 15) << 3;

    float acc[4][8];
#pragma unroll
    for (int i = 0; i < 4; i++)
#pragma unroll
        for (int j = 0; j < 8; j++) acc[i][j] = 0.0f;

    float m_i = -1e30f, l_i = 0.0f;  // softmax state for row `tid` (tid<64)

    __syncthreads();
    const int qd_first = qdoc[0];

    for (int kt = 0; kt <= qt; ++kt) {
        const int kbase = kt * BN;
        // Doc-aware skip: sorted doc ids; all keys in tile have doc <= doc[k_last].
        if (doc[kbase + BN - 1] < qd_first) continue;

        __syncthreads();  // previous PV done reading Vs/Ps

        // Load K and V tiles
        for (int i = tid; i < BN * HD_ / 4; i += 256) {
            int r = i >> 5;
            int c4 = (i & 31) << 2;
            float4 kv = *(const float4*)&K[(kbase + r) * D_ + h * HD_ + c4];
            float4 vv = *(const float4*)&V[(kbase + r) * D_ + h * HD_ + c4];
            *(float4*)&Ks[r * LDK + c4] = kv;
            *(float4*)&Vs[r * HD_ + c4] = vv;
        }
        if (tid < BN) kdoc[tid] = doc[kbase + tid];
        __syncthreads();

        // S = Qs @ Ks^T (4x4 per thread, strided)
        float s[4][4];
#pragma unroll
        for (int i = 0; i < 4; i++)
#pragma unroll
            for (int j = 0; j < 4; j++) s[i][j] = 0.0f;

        for (int d4 = 0; d4 < HD_; d4 += 4) {
            float4 qv[4], kv[4];
#pragma unroll
            for (int i = 0; i < 4; i++)
                qv[i] = *(float4*)&Qs[(sr + 16 * i) * HD_ + d4];
#pragma unroll
            for (int j = 0; j < 4; j++)
                kv[j] = *(float4*)&Ks[(sc + 16 * j) * LDK + d4];
#pragma unroll
            for (int i = 0; i < 4; i++)
#pragma unroll
                for (int j = 0; j < 4; j++) {
                    s[i][j] = fmaf(qv[i].x, kv[j].x, s[i][j]);
                    s[i][j] = fmaf(qv[i].y, kv[j].y, s[i][j]);
                    s[i][j] = fmaf(qv[i].z, kv[j].z, s[i][j]);
                    s[i][j] = fmaf(qv[i].w, kv[j].w, s[i][j]);
                }
        }

        // Mask + store S to smem
#pragma unroll
        for (int i = 0; i < 4; i++) {
            int r = sr + 16 * i;
            int gq = qbase + r;
            int dq = qdoc[r];
#pragma unroll
            for (int j = 0; j < 4; j++) {
                int c = sc + 16 * j;
                int gk = kbase + c;
                bool ok = (gk <= gq) && (kdoc[c] == dq);
                Ps[r * LDP + c] = ok ? s[i][j] : -1e30f;
            }
        }
        __syncthreads();

        // Online softmax: thread r < 64 owns row r
        if (tid < BM) {
            int r = tid;
            float mrow = -1e30f;
#pragma unroll 8
            for (int j = 0; j < BN; ++j)
                mrow = fmaxf(mrow, Ps[r * LDP + j]);
            float mnew = fmaxf(m_i, mrow);
            float resc = __expf(m_i - mnew);
            float sum = 0.0f;
#pragma unroll 8
            for (int j = 0; j < BN; ++j) {
                float sv = Ps[r * LDP + j];
                float p = (sv <= -1e29f) ? 0.0f : __expf(sv - mnew);
                Ps[r * LDP + j] = p;
                sum += p;
            }
            l_i = l_i * resc + sum;
            m_i = mnew;
            rescale[r] = resc;
        }
        __syncthreads();

        // O update: rescale accumulators, then O += P @ V
#pragma unroll
        for (int i = 0; i < 4; i++) {
            float resc = rescale[rg + 16 * i];
#pragma unroll
            for (int j = 0; j < 8; j++) acc[i][j] *= resc;
        }

        for (int j = 0; j < BN; ++j) {
            float4 v0 = *(float4*)&Vs[j * HD_ + c0];
            float4 v1 = *(float4*)&Vs[j * HD_ + c0 + 4];
#pragma unroll
            for (int i = 0; i < 4; i++) {
                float p = Ps[(rg + 16 * i) * LDP + j];
                acc[i][0] = fmaf(p, v0.x, acc[i][0]);
                acc[i][1] = fmaf(p, v0.y, acc[i][1]);
                acc[i][2] = fmaf(p, v0.z, acc[i][2]);
                acc[i][3] = fmaf(p, v0.w, acc[i][3]);
                acc[i][4] = fmaf(p, v1.x, acc[i][4]);
                acc[i][5] = fmaf(p, v1.y, acc[i][5]);
                acc[i][6] = fmaf(p, v1.z, acc[i][6]);
                acc[i][7] = fmaf(p, v1.w, acc[i][7]);
            }
        }
    }

    // Final normalization + store. Every row has >=1 valid key (diagonal).
    if (tid < BM) lrow[tid] = l_i;
    __syncthreads();

#pragma unroll
    for (int i = 0; i < 4; i++) {
        int r = rg + 16 * i;
        float inv = 1.0f / lrow[r];
        float4 o0 = make_float4(acc[i][0] * inv, acc[i][1] * inv,
                                acc[i][2] * inv, acc[i][3] * inv);
        float4 o1 = make_float4(acc[i][4] * inv, acc[i][5] * inv,
                                acc[i][6] * inv, acc[i][7] * inv);
        float* dst = &O[(qbase + r) * D_ + h * HD_ + c0];
        *(float4*)&dst[0] = o0;
        *(float4*)&dst[4] = o1;
    }
}

// ---------------------------------------------------------------------------
// Launch
// ---------------------------------------------------------------------------
extern "C" void kernel_launch(void* const* d_in, const int* in_sizes, int n_in,
                              void* d_out, int out_size)
{
    const float* x    = (const float*)d_in[0];
    const float* Wq   = (const float*)d_in[1];
    const float* Wk   = (const float*)d_in[2];
    const float* Wv   = (const float*)d_in[3];
    const float* Wo   = (const float*)d_in[4];
    const float* sint = (const float*)d_in[5];
    const float* cost = (const float*)d_in[6];
    const int*   doc  = (const int*)d_in[7];

    float *Q, *K, *V, *A;
    cudaGetSymbolAddress((void**)&Q, g_Q);
    cudaGetSymbolAddress((void**)&K, g_K);
    cudaGetSymbolAddress((void**)&V, g_V);
    cudaGetSymbolAddress((void**)&A, g_A);

    dim3 gGrid(D_ / 128, T_ / 128);  // (16,16)
    sgemm2048<<<gGrid, 256>>>(x, Wq, Q);
    sgemm2048<<<gGrid, 256>>>(x, Wk, K);
    sgemm2048<<<gGrid, 256>>>(x, Wv, V);

    int nrope = T_ * H_ * 64;
    rope_kernel<<<(nrope + 255) / 256, 256>>>(Q, K, sint, cost);

    size_t smem = (size_t)(BM * HD_ + BN * LDK + BN * HD_ + BM * LDP + 2 * BM)
                  * sizeof(float);
    cudaFuncSetAttribute(attn_kernel,
                         cudaFuncAttributeMaxDynamicSharedMemorySize, (int)smem);
    attn_kernel<<<dim3(T_ / BM, H_), 256, smem>>>(Q, K, V, doc, A);

    sgemm2048<<<gGrid, 256>>>(A, Wo, (float*)d_out);
}

// round 3
// speedup vs baseline: 2.5360x; 2.5360x over previous
#include <cuda_runtime.h>
#include <cuda_bf16.h>
#include <cstdint>
#include <math.h>

#define T_  2048
#define D_  2048
#define H_  16
#define HD_ 128

typedef __nv_bfloat16 bf16;

// ---------------------------------------------------------------------------
// Scratch (allocation-free rule: __device__ globals)
// ---------------------------------------------------------------------------
__device__ float g_Q[T_ * D_];
__device__ float g_K[T_ * D_];
__device__ float g_V[T_ * D_];
__device__ float g_A[T_ * D_];
__device__ bf16 g_xhi[T_ * D_];
__device__ bf16 g_xlo[T_ * D_];
__device__ bf16 g_Ahi[T_ * D_];
__device__ bf16 g_Alo[T_ * D_];
__device__ bf16 g_Wthi[4][D_ * D_];   // transposed weights [N,K], hi part
__device__ bf16 g_Wtlo[4][D_ * D_];   // transposed weights [N,K], lo part

// ---------------------------------------------------------------------------
// PTX helpers (compute_103-safe: mma.sync / ldmatrix / cp.async only)
// ---------------------------------------------------------------------------
__device__ __forceinline__ uint32_t smem_u32(const void* p) {
    uint32_t a;
    asm("{ .reg .u64 t; cvta.to.shared.u64 t, %1; cvt.u32.u64 %0, t; }"
        : "=r"(a) : "l"(p));
    return a;
}

#define CPA16(dst, src) \
    asm volatile("cp.async.cg.shared.global [%0], [%1], 16;" :: "r"(dst), "l"(src) : "memory")
#define CPA_COMMIT() asm volatile("cp.async.commit_group;" ::: "memory")
#define CPA_WAIT(n)  asm volatile("cp.async.wait_group %0;" :: "n"(n) : "memory")

__device__ __forceinline__ void ldsm_x4(uint32_t* r, uint32_t addr) {
    asm volatile("ldmatrix.sync.aligned.m8n8.x4.shared.b16 {%0,%1,%2,%3}, [%4];"
                 : "=r"(r[0]), "=r"(r[1]), "=r"(r[2]), "=r"(r[3]) : "r"(addr));
}

__device__ __forceinline__ void mma_bf16(float* d, const uint32_t* a,
                                         const uint32_t* b) {
    asm volatile(
        "mma.sync.aligned.m16n8k16.row.col.f32.bf16.bf16.f32 "
        "{%0,%1,%2,%3}, {%4,%5,%6,%7}, {%8,%9}, {%0,%1,%2,%3};"
        : "+f"(d[0]), "+f"(d[1]), "+f"(d[2]), "+f"(d[3])
        : "r"(a[0]), "r"(a[1]), "r"(a[2]), "r"(a[3]), "r"(b[0]), "r"(b[1]));
}

// ---------------------------------------------------------------------------
// Split fp32 -> (hi, lo) bf16, row-major
// ---------------------------------------------------------------------------
__global__ __launch_bounds__(256) void split_kernel(const float* __restrict__ src,
                                                    bf16* __restrict__ hi,
                                                    bf16* __restrict__ lo)
{
    int i = blockIdx.x * 256 + threadIdx.x;
    if (i >= T_ * D_) return;
    float v = src[i];
    bf16 h = __float2bfloat16(v);
    float r = v - __bfloat162float(h);
    hi[i] = h;
    lo[i] = __float2bfloat16(r);
}

// ---------------------------------------------------------------------------
// Transpose + split: W[K,N] fp32 -> Thi/Tlo[N,K] bf16
// ---------------------------------------------------------------------------
__global__ __launch_bounds__(256) void transpose_split(const float* __restrict__ W,
                                                       bf16* __restrict__ Thi,
                                                       bf16* __restrict__ Tlo)
{
    __shared__ float tile[32][33];
    int bx = blockIdx.x * 32;   // N block
    int by = blockIdx.y * 32;   // K block
    int tx = threadIdx.x;
    int ty = threadIdx.y;       // block (32, 8)
#pragma unroll
    for (int j = 0; j < 32; j += 8)
        tile[ty + j][tx] = W[(size_t)(by + ty + j) * D_ + bx + tx];
    __syncthreads();
#pragma unroll
    for (int j = 0; j < 32; j += 8) {
        float v = tile[tx][ty + j];
        bf16 h = __float2bfloat16(v);
        float r = v - __bfloat162float(h);
        size_t o = (size_t)(bx + ty + j) * D_ + by + tx;
        Thi[o] = h;
        Tlo[o] = __float2bfloat16(r);
    }
}

// ---------------------------------------------------------------------------
// Tensor-core GEMM via mma.sync (HMMA): C = A @ Bt^T, split-bf16 3-MMA.
// A parts: [M,K] bf16 row-major. B parts: [N,K] bf16 row-major (transposed W).
// CTA tile 128x128, BK=64, 8 warps x (64x32) warp tiles, 3-stage cp.async.
// blockIdx.z selects among up to 3 (B, C) pairs (fused QKV).
// ---------------------------------------------------------------------------
#define STAGE_BYTES 65536
#define GSMEM_BYTES (3 * STAGE_BYTES)

__global__ __launch_bounds__(256) void gemm_hmma(
    const bf16* __restrict__ Ahi, const bf16* __restrict__ Alo,
    const bf16* __restrict__ Bhi_base, const bf16* __restrict__ Blo_base,
    float* C0, float* C1, float* C2)
{
    extern __shared__ char smem[];
    uint32_t sb = smem_u32(smem);
    const int tid  = threadIdx.x;
    const int wid  = tid >> 5;
    const int lane = tid & 31;
    const int wm = wid >> 2;          // 0..1  (64-row block)
    const int wn = wid & 3;           // 0..3  (32-col block)
    const int row0 = blockIdx.y * 128;
    const int col0 = blockIdx.x * 128;
    const size_t WSZ = (size_t)D_ * D_;
    const bf16* Bhi = Bhi_base + blockIdx.z * WSZ;
    const bf16* Blo = Blo_base + blockIdx.z * WSZ;
    float* C = (blockIdx.z == 0) ? C0 : (blockIdx.z == 1) ? C1 : C2;

    const char* base[4] = {
        (const char*)(Ahi + (size_t)row0 * D_),
        (const char*)(Alo + (size_t)row0 * D_),
        (const char*)(Bhi + (size_t)col0 * D_),
        (const char*)(Blo + (size_t)col0 * D_)
    };

    // One stage: 4 matrices x 128 rows x 128B (BK=64 bf16), XOR-swizzled.
    auto load_stage = [&](int c, int s) {
        uint32_t st = sb + s * STAGE_BYTES;
#pragma unroll
        for (int j = 0; j < 16; j++) {
            int m = j >> 2;
            int rem = tid + ((j & 3) << 8);
            int r = rem >> 3;
            int cb = (rem & 7) << 4;
            const char* src = base[m] + (size_t)r * (D_ * 2) + c * 128 + cb;
            uint32_t off = (uint32_t)(r * 128) + (cb ^ ((r & 7) << 4));
            CPA16(st + m * 16384 + off, src);
        }
        CPA_COMMIT();
    };

    float acc[4][4][4];
#pragma unroll
    for (int i = 0; i < 4; i++)
#pragma unroll
        for (int j = 0; j < 4; j++)
#pragma unroll
            for (int q = 0; q < 4; q++) acc[i][j][q] = 0.0f;

    load_stage(0, 0);
    load_stage(1, 1);
    load_stage(2, 2);

    for (int c = 0; c < 32; c++) {
        int s = c % 3;
        if (c <= 29) CPA_WAIT(2);
        else if (c == 30) CPA_WAIT(1);
        else CPA_WAIT(0);
        __syncthreads();

        uint32_t st   = sb + s * STAGE_BYTES;
        uint32_t sAhi = st;
        uint32_t sAlo = st + 16384;
        uint32_t sBhi = st + 32768;
        uint32_t sBlo = st + 49152;

#pragma unroll
        for (int ks = 0; ks < 4; ks++) {
            uint32_t ah[4][4], al[4][4];
#pragma unroll
            for (int i = 0; i < 4; i++) {
                int row = wm * 64 + i * 16 + (lane & 15);
                uint32_t colb = ks * 32 + ((lane >> 4) & 1) * 16;
                uint32_t off = (uint32_t)(row * 128) + (colb ^ ((row & 7) << 4));
                ldsm_x4(ah[i], sAhi + off);
                ldsm_x4(al[i], sAlo + off);
            }
            uint32_t bh[8], bl[8];
#pragma unroll
            for (int jp = 0; jp < 2; jp++) {
                int row = wn * 32 + jp * 16 + ((lane >> 4) & 1) * 8 + (lane & 7);
                uint32_t colb = ks * 32 + ((lane >> 3) & 1) * 16;
                uint32_t off = (uint32_t)(row * 128) + (colb ^ ((row & 7) << 4));
                ldsm_x4(&bh[jp * 4], sBhi + off);
                ldsm_x4(&bl[jp * 4], sBlo + off);
            }
#pragma unroll
            for (int i = 0; i < 4; i++)
#pragma unroll
                for (int j = 0; j < 4; j++) {
                    mma_bf16(acc[i][j], ah[i], &bh[j * 2]);
                    mma_bf16(acc[i][j], al[i], &bh[j * 2]);
                    mma_bf16(acc[i][j], ah[i], &bl[j * 2]);
                }
        }
        __syncthreads();
        if (c + 3 < 32) load_stage(c + 3, s);
    }

    // Epilogue: direct register -> gmem (float2 per fragment row).
    const int g = lane >> 2;
    const int t = lane & 3;
#pragma unroll
    for (int i = 0; i < 4; i++) {
#pragma unroll
        for (int j = 0; j < 4; j++) {
            int row = row0 + wm * 64 + i * 16 + g;
            int col = col0 + wn * 32 + j * 8 + 2 * t;
            *(float2*)&C[(size_t)row * D_ + col] =
                make_float2(acc[i][j][0], acc[i][j][1]);
            *(float2*)&C[(size_t)(row + 8) * D_ + col] =
                make_float2(acc[i][j][2], acc[i][j][3]);
        }
    }
}

// ---------------------------------------------------------------------------
// RoPE (in-place) on Q and K.
// ---------------------------------------------------------------------------
__global__ __launch_bounds__(256) void rope_kernel(float* __restrict__ Q,
                                                   float* __restrict__ K,
                                                   const float* __restrict__ sin_t,
                                                   const float* __restrict__ cos_t)
{
    int idx = blockIdx.x * blockDim.x + threadIdx.x;
    if (idx >= T_ * H_ * 64) return;
    int d = idx & 63;
    int h = (idx >> 6) & (H_ - 1);
    int t = idx >> 10;
    int base = t * D_ + h * HD_;

    float s1 = sin_t[t * HD_ + d];
    float c1 = cos_t[t * HD_ + d];
    float s2 = sin_t[t * HD_ + d + 64];
    float c2 = cos_t[t * HD_ + d + 64];

    float q1 = Q[base + d];
    float q2 = Q[base + d + 64];
    Q[base + d]      = q1 * c1 - q2 * s1;
    Q[base + d + 64] = q2 * c2 + q1 * s2;

    float k1 = K[base + d];
    float k2 = K[base + d + 64];
    K[base + d]      = k1 * c1 - k2 * s1;
    K[base + d + 64] = k2 * c2 + k1 * s2;
}

// ---------------------------------------------------------------------------
// Flash-style attention with causal + same-doc mask.
// ---------------------------------------------------------------------------
#define BM 64
#define BN 64
#define LDK 132
#define LDP 65

__global__ __launch_bounds__(256) void attn_kernel(const float* __restrict__ Q,
                                                   const float* __restrict__ K,
                                                   const float* __restrict__ V,
                                                   const int* __restrict__ doc,
                                                   float* __restrict__ O)
{
    extern __shared__ float sm[];
    float* Qs = sm;
    float* Ks = Qs + BM * HD_;
    float* Vs = Ks + BN * LDK;
    float* Ps = Vs + BN * HD_;
    float* rescale = Ps + BM * LDP;
    float* lrow = rescale + BM;
    __shared__ int qdoc[BM];
    __shared__ int kdoc[BN];

    const int h = blockIdx.y;
    const int qt = blockIdx.x;
    const int qbase = qt * BM;
    const int tid = threadIdx.x;

    const float scale = 0.08838834764831845f;

    for (int i = tid; i < BM * HD_ / 4; i += 256) {
        int r = i >> 5;
        int c4 = (i & 31) << 2;
        float4 v = *(const float4*)&Q[(qbase + r) * D_ + h * HD_ + c4];
        v.x *= scale; v.y *= scale; v.z *= scale; v.w *= scale;
        *(float4*)&Qs[r * HD_ + c4] = v;
    }
    if (tid < BM) qdoc[tid] = doc[qbase + tid];

    const int sr = tid >> 4;
    const int sc = tid & 15;
    const int rg = tid >> 4;
    const int c0 = (tid & 15) << 3;

    float acc[4][8];
#pragma unroll
    for (int i = 0; i < 4; i++)
#pragma unroll
        for (int j = 0; j < 8; j++) acc[i][j] = 0.0f;

    float m_i = -1e30f, l_i = 0.0f;

    __syncthreads();
    const int qd_first = qdoc[0];

    for (int kt = 0; kt <= qt; ++kt) {
        const int kbase = kt * BN;
        if (doc[kbase + BN - 1] < qd_first) continue;

        __syncthreads();

        for (int i = tid; i < BN * HD_ / 4; i += 256) {
            int r = i >> 5;
            int c4 = (i & 31) << 2;
            float4 kv = *(const float4*)&K[(kbase + r) * D_ + h * HD_ + c4];
            float4 vv = *(const float4*)&V[(kbase + r) * D_ + h * HD_ + c4];
            *(float4*)&Ks[r * LDK + c4] = kv;
            *(float4*)&Vs[r * HD_ + c4] = vv;
        }
        if (tid < BN) kdoc[tid] = doc[kbase + tid];
        __syncthreads();

        float s[4][4];
#pragma unroll
        for (int i = 0; i < 4; i++)
#pragma unroll
            for (int j = 0; j < 4; j++) s[i][j] = 0.0f;

        for (int d4 = 0; d4 < HD_; d4 += 4) {
            float4 qv[4], kv[4];
#pragma unroll
            for (int i = 0; i < 4; i++)
                qv[i] = *(float4*)&Qs[(sr + 16 * i) * HD_ + d4];
#pragma unroll
            for (int j = 0; j < 4; j++)
                kv[j] = *(float4*)&Ks[(sc + 16 * j) * LDK + d4];
#pragma unroll
            for (int i = 0; i < 4; i++)
#pragma unroll
                for (int j = 0; j < 4; j++) {
                    s[i][j] = fmaf(qv[i].x, kv[j].x, s[i][j]);
                    s[i][j] = fmaf(qv[i].y, kv[j].y, s[i][j]);
                    s[i][j] = fmaf(qv[i].z, kv[j].z, s[i][j]);
                    s[i][j] = fmaf(qv[i].w, kv[j].w, s[i][j]);
                }
        }

#pragma unroll
        for (int i = 0; i < 4; i++) {
            int r = sr + 16 * i;
            int gq = qbase + r;
            int dq = qdoc[r];
#pragma unroll
            for (int j = 0; j < 4; j++) {
                int c = sc + 16 * j;
                int gk = kbase + c;
                bool ok = (gk <= gq) && (kdoc[c] == dq);
                Ps[r * LDP + c] = ok ? s[i][j] : -1e30f;
            }
        }
        __syncthreads();

        if (tid < BM) {
            int r = tid;
            float mrow = -1e30f;
#pragma unroll 8
            for (int j = 0; j < BN; ++j)
                mrow = fmaxf(mrow, Ps[r * LDP + j]);
            float mnew = fmaxf(m_i, mrow);
            float resc = __expf(m_i - mnew);
            float sum = 0.0f;
#pragma unroll 8
            for (int j = 0; j < BN; ++j) {
                float sv = Ps[r * LDP + j];
                float p = (sv <= -1e29f) ? 0.0f : __expf(sv - mnew);
                Ps[r * LDP + j] = p;
                sum += p;
            }
            l_i = l_i * resc + sum;
            m_i = mnew;
            rescale[r] = resc;
        }
        __syncthreads();

#pragma unroll
        for (int i = 0; i < 4; i++) {
            float resc = rescale[rg + 16 * i];
#pragma unroll
            for (int j = 0; j < 8; j++) acc[i][j] *= resc;
        }

        for (int j = 0; j < BN; ++j) {
            float4 v0 = *(float4*)&Vs[j * HD_ + c0];
            float4 v1 = *(float4*)&Vs[j * HD_ + c0 + 4];
#pragma unroll
            for (int i = 0; i < 4; i++) {
                float p = Ps[(rg + 16 * i) * LDP + j];
                acc[i][0] = fmaf(p, v0.x, acc[i][0]);
                acc[i][1] = fmaf(p, v0.y, acc[i][1]);
                acc[i][2] = fmaf(p, v0.z, acc[i][2]);
                acc[i][3] = fmaf(p, v0.w, acc[i][3]);
                acc[i][4] = fmaf(p, v1.x, acc[i][4]);
                acc[i][5] = fmaf(p, v1.y, acc[i][5]);
                acc[i][6] = fmaf(p, v1.z, acc[i][6]);
                acc[i][7] = fmaf(p, v1.w, acc[i][7]);
            }
        }
    }

    if (tid < BM) lrow[tid] = l_i;
    __syncthreads();

#pragma unroll
    for (int i = 0; i < 4; i++) {
        int r = rg + 16 * i;
        float inv = 1.0f / lrow[r];
        float4 o0 = make_float4(acc[i][0] * inv, acc[i][1] * inv,
                                acc[i][2] * inv, acc[i][3] * inv);
        float4 o1 = make_float4(acc[i][4] * inv, acc[i][5] * inv,
                                acc[i][6] * inv, acc[i][7] * inv);
        float* dst = &O[(qbase + r) * D_ + h * HD_ + c0];
        *(float4*)&dst[0] = o0;
        *(float4*)&dst[4] = o1;
    }
}

// ---------------------------------------------------------------------------
// Launch
// ---------------------------------------------------------------------------
extern "C" void kernel_launch(void* const* d_in, const int* in_sizes, int n_in,
                              void* d_out, int out_size)
{
    const float* x    = (const float*)d_in[0];
    const float* Wq   = (const float*)d_in[1];
    const float* Wk   = (const float*)d_in[2];
    const float* Wv   = (const float*)d_in[3];
    const float* Wo   = (const float*)d_in[4];
    const float* sint = (const float*)d_in[5];
    const float* cost = (const float*)d_in[6];
    const int*   doc  = (const int*)d_in[7];

    float *Q, *K, *V, *A;
    bf16 *xhi, *xlo, *Ahi, *Alo, *Wthi, *Wtlo;
    cudaGetSymbolAddress((void**)&Q, g_Q);
    cudaGetSymbolAddress((void**)&K, g_K);
    cudaGetSymbolAddress((void**)&V, g_V);
    cudaGetSymbolAddress((void**)&A, g_A);
    cudaGetSymbolAddress((void**)&xhi, g_xhi);
    cudaGetSymbolAddress((void**)&xlo, g_xlo);
    cudaGetSymbolAddress((void**)&Ahi, g_Ahi);
    cudaGetSymbolAddress((void**)&Alo, g_Alo);
    cudaGetSymbolAddress((void**)&Wthi, g_Wthi);
    cudaGetSymbolAddress((void**)&Wtlo, g_Wtlo);

    const size_t WSZ = (size_t)D_ * D_;
    const int NELEM = T_ * D_;

    split_kernel<<<(NELEM + 255) / 256, 256>>>(x, xhi, xlo);
    dim3 tsGrid(D_ / 32, D_ / 32), tsBlk(32, 8);
    transpose_split<<<tsGrid, tsBlk>>>(Wq, Wthi + 0 * WSZ, Wtlo + 0 * WSZ);
    transpose_split<<<tsGrid, tsBlk>>>(Wk, Wthi + 1 * WSZ, Wtlo + 1 * WSZ);
    transpose_split<<<tsGrid, tsBlk>>>(Wv, Wthi + 2 * WSZ, Wtlo + 2 * WSZ);
    transpose_split<<<tsGrid, tsBlk>>>(Wo, Wthi + 3 * WSZ, Wtlo + 3 * WSZ);

    cudaFuncSetAttribute(gemm_hmma,
                         cudaFuncAttributeMaxDynamicSharedMemorySize, GSMEM_BYTES);

    // Fused QKV: grid.z selects weight/output.
    dim3 gGridQKV(D_ / 128, T_ / 128, 3);
    gemm_hmma<<<gGridQKV, 256, GSMEM_BYTES>>>(xhi, xlo, Wthi, Wtlo, Q, K, V);

    int nrope = T_ * H_ * 64;
    rope_kernel<<<(nrope + 255) / 256, 256>>>(Q, K, sint, cost);

    size_t smem = (size_t)(BM * HD_ + BN * LDK + BN * HD_ + BM * LDP + 2 * BM)
                  * sizeof(float);
    cudaFuncSetAttribute(attn_kernel,
                         cudaFuncAttributeMaxDynamicSharedMemorySize, (int)smem);
    attn_kernel<<<dim3(T_ / BM, H_), 256, smem>>>(Q, K, V, doc, A);

    split_kernel<<<(NELEM + 255) / 256, 256>>>(A, Ahi, Alo);
    dim3 gGridO(D_ / 128, T_ / 128, 1);
    gemm_hmma<<<gGridO, 256, GSMEM_BYTES>>>(Ahi, Alo, Wthi + 3 * WSZ, Wtlo + 3 * WSZ,
                                            (float*)d_out, nullptr, nullptr);
}